// round 11
// baseline (speedup 1.0000x reference)
#include <cuda_runtime.h>
#include <cuda_bf16.h>

// Recall_53077205844588: masked mean of remapped `predicted` over gt!=0.
// predicted: [B=32, F=512, T=2048] fp32; gt: same shape int32 in {0,1}.
// result = sum_{gt!=0} predicted[b, f==0?1:f, t==0?1:t] / count, or 0 if count==0.
//
// Proven-best shape (sweep): 2048 blocks x 256 threads x 16 iters = 43.5us.
// This round's single change: request 36KB UNUSED dynamic shared memory at
// launch to cap occupancy at 6 CTAs/SM (vs 8). 48 warps/SM still fully covers
// DRAM latency; the goal is fewer independent per-CTA load fronts contending
// in the per-SM L1tex wavefront queue (B300 spread model: spr ~ oe*MLP_p1).
//
// Contiguous-per-block mapping: block owns 4096 consecutive float4s; thread t,
// iter i reads base + i*256 + t -> per-iter offsets i*4KB fit LDG immediates
// (zero per-iteration address ALU, 2 base regs). Remap predicates hoisted:
//   f==0 rows: blocks blockIdx%64==0, iterations 0..1 only (+512 float4 shift)
//   t==0 lane: tid==0, even iterations only (p.x <- p.y)
// __launch_bounds__(256, 8) pins regs<=32.

#define F_DIM 512
#define T_DIM 2048
#define N_VEC   8388608                       // total float4 groups
#define NTHREADS 256
#define VEC_PER_BLOCK 4096                    // 16 iters * 256 threads
#define NBLOCKS (N_VEC / VEC_PER_BLOCK)       // 2048
#define ITERS 16
#define BLOCKS_PER_IMAGE 64                   // 512*512 float4 / 4096
#define OCC_CAP_SMEM 36864                    // 36KB dynamic smem -> 6 CTAs/SM

__device__ float        g_partial_sum[NBLOCKS];
__device__ unsigned int g_partial_cnt[NBLOCKS];
__device__ unsigned int g_done_counter = 0;   // atomicInc wraps to 0 -> graph-replay safe

__device__ __forceinline__ void block_reduce_write(float v, unsigned int c,
                                                   float* out_s, unsigned int* out_c)
{
    #pragma unroll
    for (int off = 16; off > 0; off >>= 1) {
        v += __shfl_down_sync(0xffffffffu, v, off);
        c += __shfl_down_sync(0xffffffffu, c, off);
    }
    __shared__ float        s_sum[NTHREADS / 32];
    __shared__ unsigned int s_cnt[NTHREADS / 32];
    const int lane = threadIdx.x & 31;
    const int wid  = threadIdx.x >> 5;
    if (lane == 0) { s_sum[wid] = v; s_cnt[wid] = c; }
    __syncthreads();
    if (wid == 0) {
        float        bs = (lane < NTHREADS / 32) ? s_sum[lane] : 0.0f;
        unsigned int bc = (lane < NTHREADS / 32) ? s_cnt[lane] : 0u;
        #pragma unroll
        for (int off = 4; off > 0; off >>= 1) {
            bs += __shfl_down_sync(0xffffffffu, bs, off);
            bc += __shfl_down_sync(0xffffffffu, bc, off);
        }
        if (lane == 0) { *out_s = bs; *out_c = bc; }
    }
    __syncthreads();
}

__global__ __launch_bounds__(NTHREADS, 8) void recall_fused_kernel(
    const float* __restrict__ pred,
    const int*   __restrict__ gt,
    float*       __restrict__ out)
{
    const int tid  = threadIdx.x;
    const int base = blockIdx.x * VEC_PER_BLOCK + tid;      // float4 index of iter 0

    // Image = 512 rows * 512 float4 = 64 blocks. f==0 (first row of an image)
    // hits only blocks with blockIdx%64==0, within them iterations 0..1
    // (one row = 512 float4 = 2 iterations of 256 threads).
    const bool f0b = (blockIdx.x & (BLOCKS_PER_IMAGE - 1)) == 0;
    // t==0 for vector lane .x: (i*256 + tid) % 512 == 0 -> tid==0 and i even.
    const bool t0b = (tid == 0);

    const float4* pp    = (const float4*)pred + base;
    const float4* pp_f0 = pp + (T_DIM / 4);                 // row f=0 -> f=1 (+512 float4)
    const int4*   gp    = (const int4*)gt + base;

    float        local_sum = 0.0f;
    unsigned int local_cnt = 0;

    #pragma unroll
    for (int i = 0; i < ITERS; i++) {
        const float4* src = (i < 2 && f0b) ? pp_f0 : pp;    // i<2 compile-time
        float4 p = __ldcs(src + i * NTHREADS);              // offset i*4KB: immediate
        int4   g = __ldcs(gp  + i * NTHREADS);

        if (((i & 1) == 0) && t0b) p.x = p.y;               // col remap t==0 -> t'=1

        if (g.x) { local_sum += p.x; local_cnt++; }
        if (g.y) { local_sum += p.y; local_cnt++; }
        if (g.z) { local_sum += p.z; local_cnt++; }
        if (g.w) { local_sum += p.w; local_cnt++; }
    }

    float        blk_sum;
    unsigned int blk_cnt;
    block_reduce_write(local_sum, local_cnt, &blk_sum, &blk_cnt);

    __shared__ bool s_is_last;
    if (threadIdx.x == 0) {
        g_partial_sum[blockIdx.x] = blk_sum;
        g_partial_cnt[blockIdx.x] = blk_cnt;
        __threadfence();
        unsigned int prev = atomicInc(&g_done_counter, NBLOCKS - 1);
        s_is_last = (prev == NBLOCKS - 1);
    }
    __syncthreads();

    if (s_is_last) {
        float        fs = 0.0f;
        unsigned int fc = 0;
        #pragma unroll
        for (int j = 0; j < NBLOCKS / NTHREADS; j++) {
            const int idx = j * NTHREADS + threadIdx.x;
            fs += g_partial_sum[idx];
            fc += g_partial_cnt[idx];
        }
        float        tot_sum;
        unsigned int tot_cnt;
        block_reduce_write(fs, fc, &tot_sum, &tot_cnt);
        if (threadIdx.x == 0) {
            out[0] = (tot_cnt > 0u) ? (tot_sum / (float)tot_cnt) : 0.0f;
        }
    }
}

extern "C" void kernel_launch(void* const* d_in, const int* in_sizes, int n_in,
                              void* d_out, int out_size)
{
    const float* pred = (const float*)d_in[0];
    const int*   gt   = (const int*)d_in[1];
    float*       out  = (float*)d_out;

    // 36KB unused dynamic smem caps occupancy at 6 CTAs/SM (occupancy experiment).
    recall_fused_kernel<<<NBLOCKS, NTHREADS, OCC_CAP_SMEM>>>(pred, gt, out);
}

// round 12
// speedup vs baseline: 1.1736x; 1.1736x over previous
#include <cuda_runtime.h>
#include <cuda_bf16.h>

// Recall_53077205844588: masked mean of remapped `predicted` over gt!=0.
// predicted: [B=32, F=512, T=2048] fp32; gt: same shape int32 in {0,1}.
// result = sum_{gt!=0} predicted[b, f==0?1:f, t==0?1:t] / count, or 0 if count==0.
//
// FINAL proven shape (full sweep): 2048 blocks x 256 threads x 16 iters,
// occupancy 8 CTAs/SM. (1024 blk: 44.9us, 4096 blk: 45.8us, 512 thr: 45.1us,
// occ-6 cap: 57.1us -> max in-flight loads wins; 2048x256 @ occ8 = 43.5us.)
// Contiguous-per-block mapping: per-iter offsets i*4KB fit LDG immediates
// (zero per-iteration address ALU). Remap predicates hoisted:
//   f==0 rows: blocks blockIdx%64==0, iterations 0..1 only (+512 float4 shift)
//   t==0 lane: tid==0, even iterations only (p.x <- p.y)
// Accumulation is branch-free: bitwise AND mask (LOP3+FADD) + integer count.

#define F_DIM 512
#define T_DIM 2048
#define N_VEC   8388608                       // total float4 groups
#define NTHREADS 256
#define VEC_PER_BLOCK 4096                    // 16 iters * 256 threads
#define NBLOCKS (N_VEC / VEC_PER_BLOCK)       // 2048
#define ITERS 16
#define BLOCKS_PER_IMAGE 64                   // 512*512 float4 / 4096

__device__ float        g_partial_sum[NBLOCKS];
__device__ unsigned int g_partial_cnt[NBLOCKS];
__device__ unsigned int g_done_counter = 0;   // atomicInc wraps to 0 -> graph-replay safe

__device__ __forceinline__ float mask_val(float p, int g)
{
    // gt != 0 -> keep p, else 0.0f. Branch-free: LOP3 + (consumer FADD).
    int m = (g != 0) ? -1 : 0;                // compiles to ISETP/sign trick
    return __int_as_float(__float_as_int(p) & m);
}

__device__ __forceinline__ void block_reduce_write(float v, unsigned int c,
                                                   float* out_s, unsigned int* out_c)
{
    #pragma unroll
    for (int off = 16; off > 0; off >>= 1) {
        v += __shfl_down_sync(0xffffffffu, v, off);
        c += __shfl_down_sync(0xffffffffu, c, off);
    }
    __shared__ float        s_sum[NTHREADS / 32];
    __shared__ unsigned int s_cnt[NTHREADS / 32];
    const int lane = threadIdx.x & 31;
    const int wid  = threadIdx.x >> 5;
    if (lane == 0) { s_sum[wid] = v; s_cnt[wid] = c; }
    __syncthreads();
    if (wid == 0) {
        float        bs = (lane < NTHREADS / 32) ? s_sum[lane] : 0.0f;
        unsigned int bc = (lane < NTHREADS / 32) ? s_cnt[lane] : 0u;
        #pragma unroll
        for (int off = 4; off > 0; off >>= 1) {
            bs += __shfl_down_sync(0xffffffffu, bs, off);
            bc += __shfl_down_sync(0xffffffffu, bc, off);
        }
        if (lane == 0) { *out_s = bs; *out_c = bc; }
    }
    __syncthreads();
}

__global__ __launch_bounds__(NTHREADS, 8) void recall_fused_kernel(
    const float* __restrict__ pred,
    const int*   __restrict__ gt,
    float*       __restrict__ out)
{
    const int tid  = threadIdx.x;
    const int base = blockIdx.x * VEC_PER_BLOCK + tid;      // float4 index of iter 0

    // Image = 512 rows * 512 float4 = 64 blocks. f==0 (first row of an image)
    // hits only blocks with blockIdx%64==0, within them iterations 0..1
    // (one row = 512 float4 = 2 iterations of 256 threads).
    const bool f0b = (blockIdx.x & (BLOCKS_PER_IMAGE - 1)) == 0;
    // t==0 for vector lane .x: (i*256 + tid) % 512 == 0 -> tid==0 and i even.
    const bool t0b = (tid == 0);

    const float4* pp    = (const float4*)pred + base;
    const float4* pp_f0 = pp + (T_DIM / 4);                 // row f=0 -> f=1 (+512 float4)
    const int4*   gp    = (const int4*)gt + base;

    float        local_sum = 0.0f;
    unsigned int local_cnt = 0;

    #pragma unroll
    for (int i = 0; i < ITERS; i++) {
        const float4* src = (i < 2 && f0b) ? pp_f0 : pp;    // i<2 compile-time
        float4 p = __ldcs(src + i * NTHREADS);              // offset i*4KB: immediate
        int4   g = __ldcs(gp  + i * NTHREADS);

        if (((i & 1) == 0) && t0b) p.x = p.y;               // col remap t==0 -> t'=1

        local_sum += mask_val(p.x, g.x);
        local_sum += mask_val(p.y, g.y);
        local_sum += mask_val(p.z, g.z);
        local_sum += mask_val(p.w, g.w);
        // gt values are {0,1} on this dataset: count = direct integer sum.
        local_cnt += (unsigned)(g.x + g.y + g.z + g.w);
    }

    float        blk_sum;
    unsigned int blk_cnt;
    block_reduce_write(local_sum, local_cnt, &blk_sum, &blk_cnt);

    __shared__ bool s_is_last;
    if (threadIdx.x == 0) {
        g_partial_sum[blockIdx.x] = blk_sum;
        g_partial_cnt[blockIdx.x] = blk_cnt;
        __threadfence();
        unsigned int prev = atomicInc(&g_done_counter, NBLOCKS - 1);
        s_is_last = (prev == NBLOCKS - 1);
    }
    __syncthreads();

    if (s_is_last) {
        float        fs = 0.0f;
        unsigned int fc = 0;
        #pragma unroll
        for (int j = 0; j < NBLOCKS / NTHREADS; j++) {
            const int idx = j * NTHREADS + threadIdx.x;
            fs += g_partial_sum[idx];
            fc += g_partial_cnt[idx];
        }
        float        tot_sum;
        unsigned int tot_cnt;
        block_reduce_write(fs, fc, &tot_sum, &tot_cnt);
        if (threadIdx.x == 0) {
            out[0] = (tot_cnt > 0u) ? (tot_sum / (float)tot_cnt) : 0.0f;
        }
    }
}

extern "C" void kernel_launch(void* const* d_in, const int* in_sizes, int n_in,
                              void* d_out, int out_size)
{
    const float* pred = (const float*)d_in[0];
    const int*   gt   = (const int*)d_in[1];
    float*       out  = (float*)d_out;

    recall_fused_kernel<<<NBLOCKS, NTHREADS>>>(pred, gt, out);
}

// round 13
// speedup vs baseline: 1.3252x; 1.1292x over previous
#include <cuda_runtime.h>
#include <cuda_bf16.h>

// Recall_53077205844588: masked mean of remapped `predicted` over gt!=0.
// predicted: [B=32, F=512, T=2048] fp32; gt: same shape int32 in {0,1}.
// result = sum_{gt!=0} predicted[b, f==0?1:f, t==0?1:t] / count, or 0 if count==0.
//
// FINAL configuration — empirical minimum of the full sweep:
//   2048 blocks x 256 threads x 16 iters, occ 8 CTAs/SM, predicated accumulate.
//   (1024 blk: 44.9us | 4096 blk: 45.8us | 512 thr: 45.1us | occ-6: 57.1us |
//    unroll-8/addr-regs: 47.6us | bitwise mask: 48.7us | THIS: 43.5us)
// Contiguous-per-block mapping: block owns 4096 consecutive float4s; thread t,
// iter i reads base + i*256 + t -> per-iter offsets i*4KB fit LDG immediates
// (zero per-iteration address ALU, 2 base regs). Remap predicates hoisted:
//   f==0 rows: blocks blockIdx%64==0, iterations 0..1 only (+512 float4 shift)
//   t==0 lane: tid==0, even iterations only (p.x <- p.y)
// __launch_bounds__(256, 8) pins regs<=32.

#define F_DIM 512
#define T_DIM 2048
#define N_VEC   8388608                       // total float4 groups
#define NTHREADS 256
#define VEC_PER_BLOCK 4096                    // 16 iters * 256 threads
#define NBLOCKS (N_VEC / VEC_PER_BLOCK)       // 2048
#define ITERS 16
#define BLOCKS_PER_IMAGE 64                   // 512*512 float4 / 4096

__device__ float        g_partial_sum[NBLOCKS];
__device__ unsigned int g_partial_cnt[NBLOCKS];
__device__ unsigned int g_done_counter = 0;   // atomicInc wraps to 0 -> graph-replay safe

__device__ __forceinline__ void block_reduce_write(float v, unsigned int c,
                                                   float* out_s, unsigned int* out_c)
{
    #pragma unroll
    for (int off = 16; off > 0; off >>= 1) {
        v += __shfl_down_sync(0xffffffffu, v, off);
        c += __shfl_down_sync(0xffffffffu, c, off);
    }
    __shared__ float        s_sum[NTHREADS / 32];
    __shared__ unsigned int s_cnt[NTHREADS / 32];
    const int lane = threadIdx.x & 31;
    const int wid  = threadIdx.x >> 5;
    if (lane == 0) { s_sum[wid] = v; s_cnt[wid] = c; }
    __syncthreads();
    if (wid == 0) {
        float        bs = (lane < NTHREADS / 32) ? s_sum[lane] : 0.0f;
        unsigned int bc = (lane < NTHREADS / 32) ? s_cnt[lane] : 0u;
        #pragma unroll
        for (int off = 4; off > 0; off >>= 1) {
            bs += __shfl_down_sync(0xffffffffu, bs, off);
            bc += __shfl_down_sync(0xffffffffu, bc, off);
        }
        if (lane == 0) { *out_s = bs; *out_c = bc; }
    }
    __syncthreads();
}

__global__ __launch_bounds__(NTHREADS, 8) void recall_fused_kernel(
    const float* __restrict__ pred,
    const int*   __restrict__ gt,
    float*       __restrict__ out)
{
    const int tid  = threadIdx.x;
    const int base = blockIdx.x * VEC_PER_BLOCK + tid;      // float4 index of iter 0

    // Image = 512 rows * 512 float4 = 64 blocks. f==0 (first row of an image)
    // hits only blocks with blockIdx%64==0, within them iterations 0..1
    // (one row = 512 float4 = 2 iterations of 256 threads).
    const bool f0b = (blockIdx.x & (BLOCKS_PER_IMAGE - 1)) == 0;
    // t==0 for vector lane .x: (i*256 + tid) % 512 == 0 -> tid==0 and i even.
    const bool t0b = (tid == 0);

    const float4* pp    = (const float4*)pred + base;
    const float4* pp_f0 = pp + (T_DIM / 4);                 // row f=0 -> f=1 (+512 float4)
    const int4*   gp    = (const int4*)gt + base;

    float        local_sum = 0.0f;
    unsigned int local_cnt = 0;

    #pragma unroll
    for (int i = 0; i < ITERS; i++) {
        const float4* src = (i < 2 && f0b) ? pp_f0 : pp;    // i<2 compile-time
        float4 p = __ldcs(src + i * NTHREADS);              // offset i*4KB: immediate
        int4   g = __ldcs(gp  + i * NTHREADS);

        if (((i & 1) == 0) && t0b) p.x = p.y;               // col remap t==0 -> t'=1

        if (g.x) { local_sum += p.x; local_cnt++; }
        if (g.y) { local_sum += p.y; local_cnt++; }
        if (g.z) { local_sum += p.z; local_cnt++; }
        if (g.w) { local_sum += p.w; local_cnt++; }
    }

    float        blk_sum;
    unsigned int blk_cnt;
    block_reduce_write(local_sum, local_cnt, &blk_sum, &blk_cnt);

    __shared__ bool s_is_last;
    if (threadIdx.x == 0) {
        g_partial_sum[blockIdx.x] = blk_sum;
        g_partial_cnt[blockIdx.x] = blk_cnt;
        __threadfence();
        unsigned int prev = atomicInc(&g_done_counter, NBLOCKS - 1);
        s_is_last = (prev == NBLOCKS - 1);
    }
    __syncthreads();

    if (s_is_last) {
        float        fs = 0.0f;
        unsigned int fc = 0;
        #pragma unroll
        for (int j = 0; j < NBLOCKS / NTHREADS; j++) {
            const int idx = j * NTHREADS + threadIdx.x;
            fs += g_partial_sum[idx];
            fc += g_partial_cnt[idx];
        }
        float        tot_sum;
        unsigned int tot_cnt;
        block_reduce_write(fs, fc, &tot_sum, &tot_cnt);
        if (threadIdx.x == 0) {
            out[0] = (tot_cnt > 0u) ? (tot_sum / (float)tot_cnt) : 0.0f;
        }
    }
}

extern "C" void kernel_launch(void* const* d_in, const int* in_sizes, int n_in,
                              void* d_out, int out_size)
{
    const float* pred = (const float*)d_in[0];
    const int*   gt   = (const int*)d_in[1];
    float*       out  = (float*)d_out;

    recall_fused_kernel<<<NBLOCKS, NTHREADS>>>(pred, gt, out);
}